// round 14
// baseline (speedup 1.0000x reference)
#include <cuda_runtime.h>
#include <cuda_bf16.h>
#include <cstddef>

#define BB   8
#define TT   1024
#define HH   128
#define BT   (BB*TT)
#define NC   32          // chunks per (batch,layer)
#define SS   32          // chunk size
#define LPAD 132         // smem row pitch (floats)

typedef unsigned long long ull;

// ---------------- device scratch ----------------
__device__ __align__(16) float g_Q [BT*HH];
__device__ __align__(16) float g_K [BT*HH];
__device__ __align__(16) float g_V [BT*HH];
__device__ __align__(16) float g_A [BT*HH];      // a = exp(zi) * v   (per layer)
__device__ __align__(16) float g_F [BT*HH];      // zf logits          (per layer)
__device__ __align__(16) float g_X1[BT*HH];      // layer-0 hidden output
__device__ __align__(16) float g_Attn[BT*HH];    // attn readout per layer
__device__ __align__(16) float g_Qt[BT*HH];      // q * exp(cum)
__device__ __align__(16) float g_E [BB*NC*HH];   // exp(cum_S) per (b,c,h)
__device__ __align__(16) float g_U [BB*NC*HH*HH];  // per-chunk At^T @ K
__device__ __align__(16) float g_Cb[BB*NC*HH*HH];  // C at chunk start

// ---------------- packed f32x2 helpers ----------------
__device__ __forceinline__ ull pk(float lo, float hi) {
    ull r; asm("mov.b64 %0,{%1,%2};" : "=l"(r) : "f"(lo), "f"(hi)); return r;
}
__device__ __forceinline__ void upk(ull v, float &lo, float &hi) {
    asm("mov.b64 {%0,%1},%2;" : "=f"(lo), "=f"(hi) : "l"(v));
}
__device__ __forceinline__ ull fma2(ull a, ull b, ull c) {
    ull d; asm("fma.rn.f32x2 %0,%1,%2,%3;" : "=l"(d) : "l"(a), "l"(b), "l"(c)); return d;
}
__device__ __forceinline__ ull add2(ull a, ull b) {
    ull d; asm("add.rn.f32x2 %0,%1,%2;" : "=l"(d) : "l"(a), "l"(b)); return d;
}

// ---------------- GEMM accumulation ----------------
__device__ __forceinline__ void gemm_acc(const float* xs, int rgp, int cg,
                                         const float* __restrict__ W,
                                         float acc[8][4]) {
    #pragma unroll
    for (int r = 0; r < 8; ++r) { acc[r][0]=0.f; acc[r][1]=0.f; acc[r][2]=0.f; acc[r][3]=0.f; }
    #pragma unroll 2
    for (int k4 = 0; k4 < 32; ++k4) {
        float4 xr[8];
        #pragma unroll
        for (int r = 0; r < 8; ++r)
            xr[r] = *(const float4*)&xs[(rgp*8 + r)*HH + k4*4];
        #pragma unroll
        for (int kk = 0; kk < 4; ++kk) {
            float4 w = *(const float4*)&W[(size_t)(k4*4 + kk)*HH + cg*4];
            #pragma unroll
            for (int r = 0; r < 8; ++r) {
                float xv = (kk==0) ? xr[r].x : (kk==1) ? xr[r].y : (kk==2) ? xr[r].z : xr[r].w;
                acc[r][0] = fmaf(xv, w.x, acc[r][0]);
                acc[r][1] = fmaf(xv, w.y, acc[r][1]);
                acc[r][2] = fmaf(xv, w.z, acc[r][2]);
                acc[r][3] = fmaf(xv, w.w, acc[r][3]);
            }
        }
    }
}

// MODE 0: identity -> global   MODE 2: exp * Vsrc -> global
template<int MODE>
__device__ __forceinline__ void gemm_pass(const float* xs, int row0, int rgp, int cg,
                                          const float* __restrict__ W,
                                          const float* __restrict__ bias,
                                          const float* __restrict__ Vsrc,
                                          float* __restrict__ Y) {
    float acc[8][4];
    gemm_acc(xs, rgp, cg, W, acc);
    float4 b4 = *(const float4*)&bias[cg*4];
    #pragma unroll
    for (int r = 0; r < 8; ++r) {
        size_t off = (size_t)(row0 + rgp*8 + r)*HH + cg*4;
        float4 o;
        o.x = acc[r][0] + b4.x; o.y = acc[r][1] + b4.y;
        o.z = acc[r][2] + b4.z; o.w = acc[r][3] + b4.w;
        if (MODE == 2) {
            o.x = __expf(o.x); o.y = __expf(o.y); o.z = __expf(o.z); o.w = __expf(o.w);
            float4 v = *(const float4*)&Vsrc[off];
            o.x *= v.x; o.y *= v.y; o.z *= v.z; o.w *= v.w;
        }
        *(float4*)&Y[off] = o;
    }
}

// ---------------- GEMM phase, split by pass: grid (128, 4) ----------------
// y=0: Q   y=1: K   y=2: V + A(=exp(zi)*v, v recomputed in-block)   y=3: F logits
__global__ __launch_bounds__(256) void mat_kernel(
    const float* __restrict__ X,
    const float* __restrict__ Wq, const float* __restrict__ bq,
    const float* __restrict__ Wk, const float* __restrict__ bk,
    const float* __restrict__ Wv, const float* __restrict__ bv,
    const float* __restrict__ Wi, const float* __restrict__ bi,
    const float* __restrict__ Wf, const float* __restrict__ bf) {
    __shared__ float xs[64*HH];
    const int tid = threadIdx.x;
    const int row0 = blockIdx.x * 64;
    for (int i = tid; i < 64*32; i += 256) {
        int r = i >> 5, c4 = i & 31;
        *(float4*)&xs[r*HH + c4*4] = *(const float4*)&X[(size_t)(row0 + r)*HH + c4*4];
    }
    __syncthreads();
    const int cg  = tid & 31;
    const int rgp = tid >> 5;
    const int y   = blockIdx.y;
    if (y == 0) {
        gemm_pass<0>(xs, row0, rgp, cg, Wq, bq, nullptr, g_Q);
    } else if (y == 1) {
        gemm_pass<0>(xs, row0, rgp, cg, Wk, bk, nullptr, g_K);
    } else if (y == 2) {
        float vacc[8][4];
        gemm_acc(xs, rgp, cg, Wv, vacc);
        float4 bv4 = *(const float4*)&bv[cg*4];
        #pragma unroll
        for (int r = 0; r < 8; ++r) {
            vacc[r][0] += bv4.x; vacc[r][1] += bv4.y;
            vacc[r][2] += bv4.z; vacc[r][3] += bv4.w;
            size_t off = (size_t)(row0 + rgp*8 + r)*HH + cg*4;
            *(float4*)&g_V[off] = make_float4(vacc[r][0], vacc[r][1], vacc[r][2], vacc[r][3]);
        }
        float iacc[8][4];
        gemm_acc(xs, rgp, cg, Wi, iacc);
        float4 bi4 = *(const float4*)&bi[cg*4];
        #pragma unroll
        for (int r = 0; r < 8; ++r) {
            size_t off = (size_t)(row0 + rgp*8 + r)*HH + cg*4;
            float4 o;
            o.x = __expf(iacc[r][0] + bi4.x) * vacc[r][0];
            o.y = __expf(iacc[r][1] + bi4.y) * vacc[r][1];
            o.z = __expf(iacc[r][2] + bi4.z) * vacc[r][2];
            o.w = __expf(iacc[r][3] + bi4.w) * vacc[r][3];
            *(float4*)&g_A[off] = o;
        }
    } else {
        gemm_pass<0>(xs, row0, rgp, cg, Wf, bf, nullptr, g_F);
    }
}

// Layer-1 gates from g_X1: grid (128, 2). y=0: A (reads stable g_V)  y=1: F logits
__global__ __launch_bounds__(256) void gates_kernel(
    const float* __restrict__ Wi, const float* __restrict__ bi,
    const float* __restrict__ Wf, const float* __restrict__ bf) {
    __shared__ float xs[64*HH];
    const int tid = threadIdx.x;
    const int row0 = blockIdx.x * 64;
    const float* X = (const float*)g_X1;
    for (int i = tid; i < 64*32; i += 256) {
        int r = i >> 5, c4 = i & 31;
        *(float4*)&xs[r*HH + c4*4] = *(const float4*)&X[(size_t)(row0 + r)*HH + c4*4];
    }
    __syncthreads();
    const int cg  = tid & 31;
    const int rgp = tid >> 5;
    if (blockIdx.y == 0)
        gemm_pass<2>(xs, row0, rgp, cg, Wi, bi, g_V, g_A);
    else
        gemm_pass<0>(xs, row0, rgp, cg, Wf, bf, nullptr, g_F);
}

// ---------------- chunk_local + fused cumsum: 256 CTAs ----------------
__global__ __launch_bounds__(256, 1) void chunk_local_kernel() {
    const int b = blockIdx.x >> 5, c = blockIdx.x & 31;
    const int tid = threadIdx.x;
    const size_t tb = ((size_t)b*TT + (size_t)c*SS) * HH;

    __shared__ float T1[SS][LPAD];
    __shared__ float T2[SS][LPAD];
    __shared__ float Gs[SS][SS+1];

    #pragma unroll
    for (int k = 0; k < 4; ++k) {
        int i = tid + k*256, s = i >> 5, c4 = i & 31;
        *(float4*)&T1[s][c4*4] = *(const float4*)&g_F[tb + (size_t)s*HH + c4*4];
        *(float4*)&T2[s][c4*4] = *(const float4*)&g_A[tb + (size_t)s*HH + c4*4];
    }
    __syncthreads();

    // cumsum along s for column h (tid<128)
    if (tid < 128) {
        const int h = tid;
        float cum = 0.f, e = 1.f;
        #pragma unroll 4
        for (int s = 0; s < SS; ++s) {
            cum += T1[s][h];
            e = __expf(cum);
            T1[s][h] = e;                       // e^{+cum}
            T2[s][h] *= __expf(-cum);           // At
        }
        g_E[(size_t)(b*NC + c)*HH + h] = e;
    }
    __syncthreads();

    // Qt = Q * e^{+cum} -> g_Qt
    #pragma unroll
    for (int k = 0; k < 4; ++k) {
        int i = tid + k*256, s = i >> 5, c4 = i & 31;
        float4 q = *(const float4*)&g_Q[tb + (size_t)s*HH + c4*4];
        float4 e4 = *(const float4*)&T1[s][c4*4];
        q.x *= e4.x; q.y *= e4.y; q.z *= e4.z; q.w *= e4.w;
        *(float4*)&g_Qt[tb + (size_t)s*HH + c4*4] = q;
    }
    __syncthreads();   // all T1(E) reads done

    // T1 <- K
    #pragma unroll
    for (int k = 0; k < 4; ++k) {
        int i = tid + k*256, s = i >> 5, c4 = i & 31;
        *(float4*)&T1[s][c4*4] = *(const float4*)&g_K[tb + (size_t)s*HH + c4*4];
    }
    __syncthreads();

    // U[h][j] = sum_s At[s][h] * K[s][j]
    {
        const int ty = tid >> 4, tx = tid & 15;
        const int h0 = ty*8, j0 = tx*8;
        float acc[8][8];
        #pragma unroll
        for (int r = 0; r < 8; ++r)
            #pragma unroll
            for (int q = 0; q < 8; ++q) acc[r][q] = 0.f;
        for (int s = 0; s < SS; ++s) {
            float av[8], kv[8];
            #pragma unroll
            for (int r = 0; r < 8; ++r) av[r] = T2[s][h0+r];
            #pragma unroll
            for (int q = 0; q < 8; ++q) kv[q] = T1[s][j0+q];
            #pragma unroll
            for (int r = 0; r < 8; ++r)
                #pragma unroll
                for (int q = 0; q < 8; ++q) acc[r][q] = fmaf(av[r], kv[q], acc[r][q]);
        }
        const size_t ub = (size_t)(b*NC + c) * (HH*HH);
        #pragma unroll
        for (int r = 0; r < 8; ++r) {
            *(float4*)&g_U[ub + (size_t)(h0+r)*HH + j0]     = make_float4(acc[r][0], acc[r][1], acc[r][2], acc[r][3]);
            *(float4*)&g_U[ub + (size_t)(h0+r)*HH + j0 + 4] = make_float4(acc[r][4], acc[r][5], acc[r][6], acc[r][7]);
        }
    }
    __syncthreads();

    // T1 <- Qt (same-CTA write, ordered by __syncthreads)
    #pragma unroll
    for (int k = 0; k < 4; ++k) {
        int i = tid + k*256, s = i >> 5, c4 = i & 31;
        *(float4*)&T1[s][c4*4] = *(const float4*)&g_Qt[tb + (size_t)s*HH + c4*4];
    }
    __syncthreads();

    // G[t][s] = sum_h Qt[t][h]*At[s][h], causal mask s<=t
    #pragma unroll
    for (int i2 = 0; i2 < 4; ++i2) {
        int e = tid*4 + i2, t = e >> 5, s = e & 31;
        float d0=0.f, d1=0.f, d2=0.f, d3=0.f;
        for (int h = 0; h < HH; h += 4) {
            d0 = fmaf(T1[t][h+0], T2[s][h+0], d0);
            d1 = fmaf(T1[t][h+1], T2[s][h+1], d1);
            d2 = fmaf(T1[t][h+2], T2[s][h+2], d2);
            d3 = fmaf(T1[t][h+3], T2[s][h+3], d3);
        }
        Gs[t][s] = (s <= t) ? ((d0+d1)+(d2+d3)) : 0.f;
    }
    __syncthreads();

    // T1 <- K (reload)
    #pragma unroll
    for (int k = 0; k < 4; ++k) {
        int i = tid + k*256, s = i >> 5, c4 = i & 31;
        *(float4*)&T1[s][c4*4] = *(const float4*)&g_K[tb + (size_t)s*HH + c4*4];
    }
    __syncthreads();

    // intra[t][j] = sum_s Gs[t][s]*K[s][j]
    {
        const int t = tid >> 3, j0 = (tid & 7) * 16;
        float acc[16];
        #pragma unroll
        for (int q = 0; q < 16; ++q) acc[q] = 0.f;
        for (int s = 0; s < SS; ++s) {
            float g = Gs[t][s];
            #pragma unroll
            for (int q = 0; q < 16; ++q) acc[q] = fmaf(g, T1[s][j0+q], acc[q]);
        }
        #pragma unroll
        for (int jj = 0; jj < 4; ++jj)
            *(float4*)&g_Attn[tb + (size_t)t*HH + j0 + jj*4] =
                make_float4(acc[jj*4], acc[jj*4+1], acc[jj*4+2], acc[jj*4+3]);
    }
}

// ---------------- chunk combine, 128 CTAs ----------------
__global__ __launch_bounds__(256, 1) void combine_kernel() {
    const int b  = blockIdx.x >> 4;
    const int hs = blockIdx.x & 15;
    const int tid = threadIdx.x;
    const int r  = hs*8 + (tid >> 5);
    const int c4 = tid & 31;

    const float4* U4 = (const float4*)g_U;
    float4* Cb4 = (float4*)g_Cb;
    const int elem = r*32 + c4;

    float4 C = make_float4(0.f, 0.f, 0.f, 0.f);
    size_t m0 = ((size_t)(b*NC) << 12) + elem;
    float4 u = __ldg(&U4[m0]);
    float  e = __ldg(&g_E[(size_t)(b*NC)*HH + r]);

    for (int c = 0; c < NC; ++c) {
        float4 un; float en;
        if (c + 1 < NC) {
            size_t mn = ((size_t)(b*NC + c + 1) << 12) + elem;
            un = __ldg(&U4[mn]);
            en = __ldg(&g_E[(size_t)(b*NC + c + 1)*HH + r]);
        } else { un = u; en = e; }
        Cb4[((size_t)(b*NC + c) << 12) + elem] = C;
        C.x = e*(C.x + u.x); C.y = e*(C.y + u.y);
        C.z = e*(C.z + u.z); C.w = e*(C.w + u.w);
        u = un; e = en;
    }
}

// ---------------- chunk_inter, register-tiled 4x4: attn += Qt @ Cb ----------------
__global__ __launch_bounds__(256, 1) void chunk_inter_kernel() {
    const int b = blockIdx.x >> 5, c = blockIdx.x & 31;
    const int tid = threadIdx.x;
    const size_t tb = ((size_t)b*TT + (size_t)c*SS) * HH;
    const size_t cb = (size_t)(b*NC + c) * (HH*HH);

    __shared__ float tQ[SS][LPAD];
    __shared__ float tC[32][LPAD];

    #pragma unroll
    for (int k = 0; k < 4; ++k) {
        int i = tid + k*256, s = i >> 5, c4 = i & 31;
        *(float4*)&tQ[s][c4*4] = *(const float4*)&g_Qt[tb + (size_t)s*HH + c4*4];
    }

    const int t0 = (tid >> 5) * 4;        // 4 t-rows
    const int j0 = (tid & 31) * 4;        // 4 j-cols
    float acc[4][4];
    #pragma unroll
    for (int r = 0; r < 4; ++r)
        #pragma unroll
        for (int q = 0; q < 4; ++q) acc[r][q] = 0.f;

    for (int hb = 0; hb < 4; ++hb) {
        __syncthreads();   // prior slab consumed; covers tQ load on first pass
        #pragma unroll
        for (int k = 0; k < 4; ++k) {
            int i = tid + k*256, s = i >> 5, c4 = i & 31;
            *(float4*)&tC[s][c4*4] = *(const float4*)&g_Cb[cb + (size_t)(hb*32 + s)*HH + c4*4];
        }
        __syncthreads();
        #pragma unroll 4
        for (int hh = 0; hh < 32; ++hh) {
            float4 cv = *(const float4*)&tC[hh][j0];
            float q0 = tQ[t0+0][hb*32 + hh];
            float q1 = tQ[t0+1][hb*32 + hh];
            float q2 = tQ[t0+2][hb*32 + hh];
            float q3 = tQ[t0+3][hb*32 + hh];
            acc[0][0] = fmaf(q0, cv.x, acc[0][0]); acc[0][1] = fmaf(q0, cv.y, acc[0][1]);
            acc[0][2] = fmaf(q0, cv.z, acc[0][2]); acc[0][3] = fmaf(q0, cv.w, acc[0][3]);
            acc[1][0] = fmaf(q1, cv.x, acc[1][0]); acc[1][1] = fmaf(q1, cv.y, acc[1][1]);
            acc[1][2] = fmaf(q1, cv.z, acc[1][2]); acc[1][3] = fmaf(q1, cv.w, acc[1][3]);
            acc[2][0] = fmaf(q2, cv.x, acc[2][0]); acc[2][1] = fmaf(q2, cv.y, acc[2][1]);
            acc[2][2] = fmaf(q2, cv.z, acc[2][2]); acc[2][3] = fmaf(q2, cv.w, acc[2][3]);
            acc[3][0] = fmaf(q3, cv.x, acc[3][0]); acc[3][1] = fmaf(q3, cv.y, acc[3][1]);
            acc[3][2] = fmaf(q3, cv.z, acc[3][2]); acc[3][3] = fmaf(q3, cv.w, acc[3][3]);
        }
    }

    #pragma unroll
    for (int r = 0; r < 4; ++r) {
        size_t off = tb + (size_t)(t0 + r)*HH + j0;
        float4 v = *(const float4*)&g_Attn[off];
        v.x += acc[r][0]; v.y += acc[r][1]; v.z += acc[r][2]; v.w += acc[r][3];
        *(float4*)&g_Attn[off] = v;
    }
}

// ---------------- h recurrence: TWO BATCHES PER CTA ----------------
// 256 threads = 2 groups of 128. Group g (tid>>7) runs batch 2*blk+g,
// thread j = tid&127 owns column j (full Wo column in 64 f32x2 regs).
// The two groups' independent serial chains interleave on the SM: group B's
// fma2 issue fills group A's dependency-stall shadow. Joint barrier (lockstep).
__global__ __launch_bounds__(256, 1) void hrec_kernel(
    const float* __restrict__ Wo, const float* __restrict__ bo,
    float* __restrict__ Xout_param) {
    const int tid = threadIdx.x;
    const int g   = tid >> 7;             // 0/1 batch group
    const int j   = tid & 127;            // column
    const int b   = blockIdx.x * 2 + g;
    const float NL2E = -1.44269504088896f;

    __shared__ __align__(16) float hbuf[2][2][HH];   // [group][phase][col]

    float* Xout = Xout_param ? Xout_param : g_X1;
    const size_t base = (size_t)b * TT * HH;
    const float* Attnb = g_Attn + base;

    // full Wo column, pre-scaled by -log2(e), packed over i pairs
    ull w2[64];
    #pragma unroll
    for (int p = 0; p < 64; ++p)
        w2[p] = pk(NL2E * Wo[(size_t)(2*p)*HH + j],
                   NL2E * Wo[(size_t)(2*p + 1)*HH + j]);
    const float bo2 = NL2E * bo[j];

    hbuf[g][0][j] = 0.f;

    float ring[8];
    #pragma unroll
    for (int u = 0; u < 8; ++u)
        ring[u] = __ldg(Attnb + (size_t)u*HH + j);

    for (int tb = 0; tb < TT; tb += 8) {
        #pragma unroll
        for (int u = 0; u < 8; ++u) {
            const int t = tb + u;
            __syncthreads();   // both groups' hbuf[.][t&1] (written at t-1) visible

            const ulonglong2* hb2 = (const ulonglong2*)hbuf[g][t & 1];
            ull s[8];
            #pragma unroll
            for (int q = 0; q < 8; ++q) s[q] = 0ull;
            #pragma unroll
            for (int k = 0; k < 32; ++k) {
                ulonglong2 hh = hb2[k];          // h[4k..4k+3], broadcast within group
                s[(2*k)   & 7] = fma2(hh.x, w2[2*k],     s[(2*k)   & 7]);
                s[(2*k+1) & 7] = fma2(hh.y, w2[2*k + 1], s[(2*k+1) & 7]);
            }
            ull t0 = add2(s[0], s[1]), t1 = add2(s[2], s[3]);
            ull t2 = add2(s[4], s[5]), t3 = add2(s[6], s[7]);
            ull st = add2(add2(t0, t1), add2(t2, t3));
            float lo, hi; upk(st, lo, hi);
            float zl = lo + hi + bo2;            // = -z * log2(e)
            float ex; asm("ex2.approx.f32 %0, %1;" : "=f"(ex) : "f"(zl));   // e^-z
            float den = 1.0f + ex;
            float o;  asm("rcp.approx.f32 %0, %1;" : "=f"(o) : "f"(den));
            float h = o * ring[u];
            hbuf[g][(t & 1) ^ 1][j] = h;
            Xout[base + (size_t)t*HH + j] = h;
            if (t + 8 < TT)
                ring[u] = __ldg(Attnb + (size_t)(t + 8)*HH + j);
        }
    }
}

// ---------------- launch ----------------
extern "C" void kernel_launch(void* const* d_in, const int* in_sizes, int n_in,
                              void* d_out, int out_size) {
    const float* X  = (const float*)d_in[0];
    const float* Wq = (const float*)d_in[1];
    const float* bq = (const float*)d_in[2];
    const float* Wk = (const float*)d_in[3];
    const float* bk = (const float*)d_in[4];
    const float* Wv = (const float*)d_in[5];
    const float* bv = (const float*)d_in[6];
    const float* Wi = (const float*)d_in[7];
    const float* bi = (const float*)d_in[8];
    const float* Wf = (const float*)d_in[9];
    const float* bf = (const float*)d_in[10];
    const float* Wo = (const float*)d_in[11];
    const float* bo = (const float*)d_in[12];
    float* out = (float*)d_out;

    const int LW = HH*HH;
    const int LB = HH;

    mat_kernel<<<dim3(BT/64, 4), 256>>>(X, Wq, bq, Wk, bk, Wv, bv,
                                        Wi + 0*LW, bi + 0*LB, Wf + 0*LW, bf + 0*LB);
    chunk_local_kernel<<<BB*NC, 256>>>();
    combine_kernel<<<BB*16, 256>>>();
    chunk_inter_kernel<<<BB*NC, 256>>>();
    hrec_kernel<<<BB/2, 256>>>(Wo + 0*LW, bo + 0*LB, nullptr);   // -> g_X1

    gates_kernel<<<dim3(BT/64, 2), 256>>>(Wi + 1*LW, bi + 1*LB, Wf + 1*LW, bf + 1*LB);
    chunk_local_kernel<<<BB*NC, 256>>>();
    combine_kernel<<<BB*16, 256>>>();
    chunk_inter_kernel<<<BB*NC, 256>>>();
    hrec_kernel<<<BB/2, 256>>>(Wo + 1*LW, bo + 1*LB, out);
}

// round 16
// speedup vs baseline: 1.3960x; 1.3960x over previous
#include <cuda_runtime.h>
#include <cuda_bf16.h>
#include <cstddef>

#define BB   8
#define TT   1024
#define HH   128
#define BT   (BB*TT)
#define NC   32          // chunks per (batch,layer)
#define SS   32          // chunk size
#define LPAD 132         // smem row pitch (floats)

typedef unsigned long long ull;

// ---------------- device scratch ----------------
__device__ __align__(16) float g_Q [BT*HH];
__device__ __align__(16) float g_K [BT*HH];
__device__ __align__(16) float g_V [BT*HH];
__device__ __align__(16) float g_A [BT*HH];      // a = exp(zi) * v   (per layer)
__device__ __align__(16) float g_F [BT*HH];      // zf logits          (per layer)
__device__ __align__(16) float g_X1[BT*HH];      // layer-0 hidden output
__device__ __align__(16) float g_Attn[BT*HH];    // attn readout per layer
__device__ __align__(16) float g_Qt[BT*HH];      // q * exp(cum)
__device__ __align__(16) float g_E [BB*NC*HH];   // exp(cum_S) per (b,c,h)
__device__ __align__(16) float g_U [BB*NC*HH*HH];  // per-chunk At^T @ K
__device__ __align__(16) float g_Cb[BB*NC*HH*HH];  // C at chunk start

// ---------------- packed f32x2 helpers ----------------
__device__ __forceinline__ ull pk(float lo, float hi) {
    ull r; asm("mov.b64 %0,{%1,%2};" : "=l"(r) : "f"(lo), "f"(hi)); return r;
}
__device__ __forceinline__ void upk(ull v, float &lo, float &hi) {
    asm("mov.b64 {%0,%1},%2;" : "=f"(lo), "=f"(hi) : "l"(v));
}
__device__ __forceinline__ ull fma2(ull a, ull b, ull c) {
    ull d; asm("fma.rn.f32x2 %0,%1,%2,%3;" : "=l"(d) : "l"(a), "l"(b), "l"(c)); return d;
}
__device__ __forceinline__ ull add2(ull a, ull b) {
    ull d; asm("add.rn.f32x2 %0,%1,%2;" : "=l"(d) : "l"(a), "l"(b)); return d;
}

// ---------------- GEMM accumulation ----------------
__device__ __forceinline__ void gemm_acc(const float* xs, int rgp, int cg,
                                         const float* __restrict__ W,
                                         float acc[8][4]) {
    #pragma unroll
    for (int r = 0; r < 8; ++r) { acc[r][0]=0.f; acc[r][1]=0.f; acc[r][2]=0.f; acc[r][3]=0.f; }
    #pragma unroll 2
    for (int k4 = 0; k4 < 32; ++k4) {
        float4 xr[8];
        #pragma unroll
        for (int r = 0; r < 8; ++r)
            xr[r] = *(const float4*)&xs[(rgp*8 + r)*HH + k4*4];
        #pragma unroll
        for (int kk = 0; kk < 4; ++kk) {
            float4 w = *(const float4*)&W[(size_t)(k4*4 + kk)*HH + cg*4];
            #pragma unroll
            for (int r = 0; r < 8; ++r) {
                float xv = (kk==0) ? xr[r].x : (kk==1) ? xr[r].y : (kk==2) ? xr[r].z : xr[r].w;
                acc[r][0] = fmaf(xv, w.x, acc[r][0]);
                acc[r][1] = fmaf(xv, w.y, acc[r][1]);
                acc[r][2] = fmaf(xv, w.z, acc[r][2]);
                acc[r][3] = fmaf(xv, w.w, acc[r][3]);
            }
        }
    }
}

// MODE 0: identity -> global   MODE 2: exp * Vsrc -> global
template<int MODE>
__device__ __forceinline__ void gemm_pass(const float* xs, int row0, int rgp, int cg,
                                          const float* __restrict__ W,
                                          const float* __restrict__ bias,
                                          const float* __restrict__ Vsrc,
                                          float* __restrict__ Y) {
    float acc[8][4];
    gemm_acc(xs, rgp, cg, W, acc);
    float4 b4 = *(const float4*)&bias[cg*4];
    #pragma unroll
    for (int r = 0; r < 8; ++r) {
        size_t off = (size_t)(row0 + rgp*8 + r)*HH + cg*4;
        float4 o;
        o.x = acc[r][0] + b4.x; o.y = acc[r][1] + b4.y;
        o.z = acc[r][2] + b4.z; o.w = acc[r][3] + b4.w;
        if (MODE == 2) {
            o.x = __expf(o.x); o.y = __expf(o.y); o.z = __expf(o.z); o.w = __expf(o.w);
            float4 v = *(const float4*)&Vsrc[off];
            o.x *= v.x; o.y *= v.y; o.z *= v.z; o.w *= v.w;
        }
        *(float4*)&Y[off] = o;
    }
}

// ---------------- GEMM phase, split by pass: grid (128, 4) ----------------
// y=0: Q   y=1: K   y=2: V + A(=exp(zi)*v, v recomputed in-block)   y=3: F logits
__global__ __launch_bounds__(256) void mat_kernel(
    const float* __restrict__ X,
    const float* __restrict__ Wq, const float* __restrict__ bq,
    const float* __restrict__ Wk, const float* __restrict__ bk,
    const float* __restrict__ Wv, const float* __restrict__ bv,
    const float* __restrict__ Wi, const float* __restrict__ bi,
    const float* __restrict__ Wf, const float* __restrict__ bf) {
    __shared__ float xs[64*HH];
    const int tid = threadIdx.x;
    const int row0 = blockIdx.x * 64;
    for (int i = tid; i < 64*32; i += 256) {
        int r = i >> 5, c4 = i & 31;
        *(float4*)&xs[r*HH + c4*4] = *(const float4*)&X[(size_t)(row0 + r)*HH + c4*4];
    }
    __syncthreads();
    const int cg  = tid & 31;
    const int rgp = tid >> 5;
    const int y   = blockIdx.y;
    if (y == 0) {
        gemm_pass<0>(xs, row0, rgp, cg, Wq, bq, nullptr, g_Q);
    } else if (y == 1) {
        gemm_pass<0>(xs, row0, rgp, cg, Wk, bk, nullptr, g_K);
    } else if (y == 2) {
        float vacc[8][4];
        gemm_acc(xs, rgp, cg, Wv, vacc);
        float4 bv4 = *(const float4*)&bv[cg*4];
        #pragma unroll
        for (int r = 0; r < 8; ++r) {
            vacc[r][0] += bv4.x; vacc[r][1] += bv4.y;
            vacc[r][2] += bv4.z; vacc[r][3] += bv4.w;
            size_t off = (size_t)(row0 + rgp*8 + r)*HH + cg*4;
            *(float4*)&g_V[off] = make_float4(vacc[r][0], vacc[r][1], vacc[r][2], vacc[r][3]);
        }
        float iacc[8][4];
        gemm_acc(xs, rgp, cg, Wi, iacc);
        float4 bi4 = *(const float4*)&bi[cg*4];
        #pragma unroll
        for (int r = 0; r < 8; ++r) {
            size_t off = (size_t)(row0 + rgp*8 + r)*HH + cg*4;
            float4 o;
            o.x = __expf(iacc[r][0] + bi4.x) * vacc[r][0];
            o.y = __expf(iacc[r][1] + bi4.y) * vacc[r][1];
            o.z = __expf(iacc[r][2] + bi4.z) * vacc[r][2];
            o.w = __expf(iacc[r][3] + bi4.w) * vacc[r][3];
            *(float4*)&g_A[off] = o;
        }
    } else {
        gemm_pass<0>(xs, row0, rgp, cg, Wf, bf, nullptr, g_F);
    }
}

// Layer-1 gates from g_X1: grid (128, 2). y=0: A (reads stable g_V)  y=1: F logits
__global__ __launch_bounds__(256) void gates_kernel(
    const float* __restrict__ Wi, const float* __restrict__ bi,
    const float* __restrict__ Wf, const float* __restrict__ bf) {
    __shared__ float xs[64*HH];
    const int tid = threadIdx.x;
    const int row0 = blockIdx.x * 64;
    const float* X = (const float*)g_X1;
    for (int i = tid; i < 64*32; i += 256) {
        int r = i >> 5, c4 = i & 31;
        *(float4*)&xs[r*HH + c4*4] = *(const float4*)&X[(size_t)(row0 + r)*HH + c4*4];
    }
    __syncthreads();
    const int cg  = tid & 31;
    const int rgp = tid >> 5;
    if (blockIdx.y == 0)
        gemm_pass<2>(xs, row0, rgp, cg, Wi, bi, g_V, g_A);
    else
        gemm_pass<0>(xs, row0, rgp, cg, Wf, bf, nullptr, g_F);
}

// ---------------- chunk_local + fused cumsum: 256 CTAs ----------------
__global__ __launch_bounds__(256, 1) void chunk_local_kernel() {
    const int b = blockIdx.x >> 5, c = blockIdx.x & 31;
    const int tid = threadIdx.x;
    const size_t tb = ((size_t)b*TT + (size_t)c*SS) * HH;

    __shared__ float T1[SS][LPAD];
    __shared__ float T2[SS][LPAD];
    __shared__ float Gs[SS][SS+1];

    #pragma unroll
    for (int k = 0; k < 4; ++k) {
        int i = tid + k*256, s = i >> 5, c4 = i & 31;
        *(float4*)&T1[s][c4*4] = *(const float4*)&g_F[tb + (size_t)s*HH + c4*4];
        *(float4*)&T2[s][c4*4] = *(const float4*)&g_A[tb + (size_t)s*HH + c4*4];
    }
    __syncthreads();

    // cumsum along s for column h (tid<128)
    if (tid < 128) {
        const int h = tid;
        float cum = 0.f, e = 1.f;
        #pragma unroll 4
        for (int s = 0; s < SS; ++s) {
            cum += T1[s][h];
            e = __expf(cum);
            T1[s][h] = e;                       // e^{+cum}
            T2[s][h] *= __expf(-cum);           // At
        }
        g_E[(size_t)(b*NC + c)*HH + h] = e;
    }
    __syncthreads();

    // Qt = Q * e^{+cum} -> g_Qt
    #pragma unroll
    for (int k = 0; k < 4; ++k) {
        int i = tid + k*256, s = i >> 5, c4 = i & 31;
        float4 q = *(const float4*)&g_Q[tb + (size_t)s*HH + c4*4];
        float4 e4 = *(const float4*)&T1[s][c4*4];
        q.x *= e4.x; q.y *= e4.y; q.z *= e4.z; q.w *= e4.w;
        *(float4*)&g_Qt[tb + (size_t)s*HH + c4*4] = q;
    }
    __syncthreads();   // all T1(E) reads done

    // T1 <- K
    #pragma unroll
    for (int k = 0; k < 4; ++k) {
        int i = tid + k*256, s = i >> 5, c4 = i & 31;
        *(float4*)&T1[s][c4*4] = *(const float4*)&g_K[tb + (size_t)s*HH + c4*4];
    }
    __syncthreads();

    // U[h][j] = sum_s At[s][h] * K[s][j]
    {
        const int ty = tid >> 4, tx = tid & 15;
        const int h0 = ty*8, j0 = tx*8;
        float acc[8][8];
        #pragma unroll
        for (int r = 0; r < 8; ++r)
            #pragma unroll
            for (int q = 0; q < 8; ++q) acc[r][q] = 0.f;
        for (int s = 0; s < SS; ++s) {
            float av[8], kv[8];
            #pragma unroll
            for (int r = 0; r < 8; ++r) av[r] = T2[s][h0+r];
            #pragma unroll
            for (int q = 0; q < 8; ++q) kv[q] = T1[s][j0+q];
            #pragma unroll
            for (int r = 0; r < 8; ++r)
                #pragma unroll
                for (int q = 0; q < 8; ++q) acc[r][q] = fmaf(av[r], kv[q], acc[r][q]);
        }
        const size_t ub = (size_t)(b*NC + c) * (HH*HH);
        #pragma unroll
        for (int r = 0; r < 8; ++r) {
            *(float4*)&g_U[ub + (size_t)(h0+r)*HH + j0]     = make_float4(acc[r][0], acc[r][1], acc[r][2], acc[r][3]);
            *(float4*)&g_U[ub + (size_t)(h0+r)*HH + j0 + 4] = make_float4(acc[r][4], acc[r][5], acc[r][6], acc[r][7]);
        }
    }
    __syncthreads();

    // T1 <- Qt (same-CTA write, ordered by __syncthreads)
    #pragma unroll
    for (int k = 0; k < 4; ++k) {
        int i = tid + k*256, s = i >> 5, c4 = i & 31;
        *(float4*)&T1[s][c4*4] = *(const float4*)&g_Qt[tb + (size_t)s*HH + c4*4];
    }
    __syncthreads();

    // G[t][s] = sum_h Qt[t][h]*At[s][h], causal mask s<=t
    #pragma unroll
    for (int i2 = 0; i2 < 4; ++i2) {
        int e = tid*4 + i2, t = e >> 5, s = e & 31;
        float d0=0.f, d1=0.f, d2=0.f, d3=0.f;
        for (int h = 0; h < HH; h += 4) {
            d0 = fmaf(T1[t][h+0], T2[s][h+0], d0);
            d1 = fmaf(T1[t][h+1], T2[s][h+1], d1);
            d2 = fmaf(T1[t][h+2], T2[s][h+2], d2);
            d3 = fmaf(T1[t][h+3], T2[s][h+3], d3);
        }
        Gs[t][s] = (s <= t) ? ((d0+d1)+(d2+d3)) : 0.f;
    }
    __syncthreads();

    // T1 <- K (reload)
    #pragma unroll
    for (int k = 0; k < 4; ++k) {
        int i = tid + k*256, s = i >> 5, c4 = i & 31;
        *(float4*)&T1[s][c4*4] = *(const float4*)&g_K[tb + (size_t)s*HH + c4*4];
    }
    __syncthreads();

    // intra[t][j] = sum_s Gs[t][s]*K[s][j]
    {
        const int t = tid >> 3, j0 = (tid & 7) * 16;
        float acc[16];
        #pragma unroll
        for (int q = 0; q < 16; ++q) acc[q] = 0.f;
        for (int s = 0; s < SS; ++s) {
            float g = Gs[t][s];
            #pragma unroll
            for (int q = 0; q < 16; ++q) acc[q] = fmaf(g, T1[s][j0+q], acc[q]);
        }
        #pragma unroll
        for (int jj = 0; jj < 4; ++jj)
            *(float4*)&g_Attn[tb + (size_t)t*HH + j0 + jj*4] =
                make_float4(acc[jj*4], acc[jj*4+1], acc[jj*4+2], acc[jj*4+3]);
    }
}

// ---------------- chunk combine, 128 CTAs ----------------
__global__ __launch_bounds__(256, 1) void combine_kernel() {
    const int b  = blockIdx.x >> 4;
    const int hs = blockIdx.x & 15;
    const int tid = threadIdx.x;
    const int r  = hs*8 + (tid >> 5);
    const int c4 = tid & 31;

    const float4* U4 = (const float4*)g_U;
    float4* Cb4 = (float4*)g_Cb;
    const int elem = r*32 + c4;

    float4 C = make_float4(0.f, 0.f, 0.f, 0.f);
    size_t m0 = ((size_t)(b*NC) << 12) + elem;
    float4 u = __ldg(&U4[m0]);
    float  e = __ldg(&g_E[(size_t)(b*NC)*HH + r]);

    for (int c = 0; c < NC; ++c) {
        float4 un; float en;
        if (c + 1 < NC) {
            size_t mn = ((size_t)(b*NC + c + 1) << 12) + elem;
            un = __ldg(&U4[mn]);
            en = __ldg(&g_E[(size_t)(b*NC + c + 1)*HH + r]);
        } else { un = u; en = e; }
        Cb4[((size_t)(b*NC + c) << 12) + elem] = C;
        C.x = e*(C.x + u.x); C.y = e*(C.y + u.y);
        C.z = e*(C.z + u.z); C.w = e*(C.w + u.w);
        u = un; e = en;
    }
}

// ---------------- chunk_inter, register-tiled 4x4: attn += Qt @ Cb ----------------
__global__ __launch_bounds__(256, 1) void chunk_inter_kernel() {
    const int b = blockIdx.x >> 5, c = blockIdx.x & 31;
    const int tid = threadIdx.x;
    const size_t tb = ((size_t)b*TT + (size_t)c*SS) * HH;
    const size_t cb = (size_t)(b*NC + c) * (HH*HH);

    __shared__ float tQ[SS][LPAD];
    __shared__ float tC[32][LPAD];

    #pragma unroll
    for (int k = 0; k < 4; ++k) {
        int i = tid + k*256, s = i >> 5, c4 = i & 31;
        *(float4*)&tQ[s][c4*4] = *(const float4*)&g_Qt[tb + (size_t)s*HH + c4*4];
    }

    const int t0 = (tid >> 5) * 4;        // 4 t-rows
    const int j0 = (tid & 31) * 4;        // 4 j-cols
    float acc[4][4];
    #pragma unroll
    for (int r = 0; r < 4; ++r)
        #pragma unroll
        for (int q = 0; q < 4; ++q) acc[r][q] = 0.f;

    for (int hb = 0; hb < 4; ++hb) {
        __syncthreads();   // prior slab consumed; covers tQ load on first pass
        #pragma unroll
        for (int k = 0; k < 4; ++k) {
            int i = tid + k*256, s = i >> 5, c4 = i & 31;
            *(float4*)&tC[s][c4*4] = *(const float4*)&g_Cb[cb + (size_t)(hb*32 + s)*HH + c4*4];
        }
        __syncthreads();
        #pragma unroll 4
        for (int hh = 0; hh < 32; ++hh) {
            float4 cv = *(const float4*)&tC[hh][j0];
            float q0 = tQ[t0+0][hb*32 + hh];
            float q1 = tQ[t0+1][hb*32 + hh];
            float q2 = tQ[t0+2][hb*32 + hh];
            float q3 = tQ[t0+3][hb*32 + hh];
            acc[0][0] = fmaf(q0, cv.x, acc[0][0]); acc[0][1] = fmaf(q0, cv.y, acc[0][1]);
            acc[0][2] = fmaf(q0, cv.z, acc[0][2]); acc[0][3] = fmaf(q0, cv.w, acc[0][3]);
            acc[1][0] = fmaf(q1, cv.x, acc[1][0]); acc[1][1] = fmaf(q1, cv.y, acc[1][1]);
            acc[1][2] = fmaf(q1, cv.z, acc[1][2]); acc[1][3] = fmaf(q1, cv.w, acc[1][3]);
            acc[2][0] = fmaf(q2, cv.x, acc[2][0]); acc[2][1] = fmaf(q2, cv.y, acc[2][1]);
            acc[2][2] = fmaf(q2, cv.z, acc[2][2]); acc[2][3] = fmaf(q2, cv.w, acc[2][3]);
            acc[3][0] = fmaf(q3, cv.x, acc[3][0]); acc[3][1] = fmaf(q3, cv.y, acc[3][1]);
            acc[3][2] = fmaf(q3, cv.z, acc[3][2]); acc[3][3] = fmaf(q3, cv.w, acc[3][3]);
        }
    }

    #pragma unroll
    for (int r = 0; r < 4; ++r) {
        size_t off = tb + (size_t)(t0 + r)*HH + j0;
        float4 v = *(const float4*)&g_Attn[off];
        v.x += acc[r][0]; v.y += acc[r][1]; v.z += acc[r][2]; v.w += acc[r][3];
        *(float4*)&g_Attn[off] = v;
    }
}

// ---------------- h recurrence: 128 threads, one full column per thread (R13) ----
// Thread j owns Wo[:,j] as 64 packed f32x2 registers. Per step: 32 broadcast
// LDS.128 of h + 64 independent fma2 over 8 chains (per-SMSP issue floor),
// no shfl, sigma once, 1 warp per SMSP, 8 CTAs = all batches parallel.
// Micro: bias pre-seeded into chain s[0]; ring prefetch issued before the fold.
__global__ __launch_bounds__(128, 1) void hrec_kernel(
    const float* __restrict__ Wo, const float* __restrict__ bo,
    float* __restrict__ Xout_param) {
    const int b = blockIdx.x;
    const int j = threadIdx.x;            // 0..127 column
    const float NL2E = -1.44269504088896f;

    __shared__ __align__(16) float hbuf[2][HH];

    float* Xout = Xout_param ? Xout_param : g_X1;
    const size_t base = (size_t)b * TT * HH;
    const float* Attnb = g_Attn + base;

    // full Wo column, pre-scaled by -log2(e), packed over i pairs
    ull w2[64];
    #pragma unroll
    for (int p = 0; p < 64; ++p)
        w2[p] = pk(NL2E * Wo[(size_t)(2*p)*HH + j],
                   NL2E * Wo[(size_t)(2*p + 1)*HH + j]);
    const ull bseed = pk(NL2E * bo[j], 0.f);   // bias folded into chain seed

    hbuf[0][j] = 0.f;

    float ring[8];
    #pragma unroll
    for (int u = 0; u < 8; ++u)
        ring[u] = __ldg(Attnb + (size_t)u*HH + j);

    for (int tb = 0; tb < TT; tb += 8) {
        #pragma unroll
        for (int u = 0; u < 8; ++u) {
            const int t = tb + u;
            __syncthreads();   // hbuf[t&1] (written at t-1) visible to all

            const ulonglong2* hb2 = (const ulonglong2*)hbuf[t & 1];
            ull s[8];
            s[0] = bseed;
            #pragma unroll
            for (int q = 1; q < 8; ++q) s[q] = 0ull;
            #pragma unroll
            for (int k = 0; k < 32; ++k) {
                ulonglong2 hh = hb2[k];          // h[4k..4k+3], broadcast across warp
                s[(2*k)   & 7] = fma2(hh.x, w2[2*k],     s[(2*k)   & 7]);
                s[(2*k+1) & 7] = fma2(hh.y, w2[2*k + 1], s[(2*k+1) & 7]);
            }
            // prefetch next ring entry early (off-chain LDG inside fma shadow)
            float rnext = 0.f;
            if (t + 8 < TT) rnext = __ldg(Attnb + (size_t)(t + 8)*HH + j);

            ull t0 = add2(s[0], s[1]), t1 = add2(s[2], s[3]);
            ull t2 = add2(s[4], s[5]), t3 = add2(s[6], s[7]);
            ull st = add2(add2(t0, t1), add2(t2, t3));
            float lo, hi; upk(st, lo, hi);
            float zl = lo + hi;                  // = -(z)*log2(e), bias included
            float ex; asm("ex2.approx.f32 %0, %1;" : "=f"(ex) : "f"(zl));   // e^-z
            float den = 1.0f + ex;
            float o;  asm("rcp.approx.f32 %0, %1;" : "=f"(o) : "f"(den));
            float h = o * ring[u];
            hbuf[(t & 1) ^ 1][j] = h;
            Xout[base + (size_t)t*HH + j] = h;
            ring[u] = rnext;
        }
    }
}

// ---------------- launch ----------------
extern "C" void kernel_launch(void* const* d_in, const int* in_sizes, int n_in,
                              void* d_out, int out_size) {
    const float* X  = (const float*)d_in[0];
    const float* Wq = (const float*)d_in[1];
    const float* bq = (const float*)d_in[2];
    const float* Wk = (const float*)d_in[3];
    const float* bk = (const float*)d_in[4];
    const float* Wv = (const float*)d_in[5];
    const float* bv = (const float*)d_in[6];
    const float* Wi = (const float*)d_in[7];
    const float* bi = (const float*)d_in[8];
    const float* Wf = (const float*)d_in[9];
    const float* bf = (const float*)d_in[10];
    const float* Wo = (const float*)d_in[11];
    const float* bo = (const float*)d_in[12];
    float* out = (float*)d_out;

    const int LW = HH*HH;
    const int LB = HH;

    mat_kernel<<<dim3(BT/64, 4), 256>>>(X, Wq, bq, Wk, bk, Wv, bv,
                                        Wi + 0*LW, bi + 0*LB, Wf + 0*LW, bf + 0*LB);
    chunk_local_kernel<<<BB*NC, 256>>>();
    combine_kernel<<<BB*16, 256>>>();
    chunk_inter_kernel<<<BB*NC, 256>>>();
    hrec_kernel<<<BB, 128>>>(Wo + 0*LW, bo + 0*LB, nullptr);   // -> g_X1

    gates_kernel<<<dim3(BT/64, 2), 256>>>(Wi + 1*LW, bi + 1*LB, Wf + 1*LW, bf + 1*LB);
    chunk_local_kernel<<<BB*NC, 256>>>();
    combine_kernel<<<BB*16, 256>>>();
    chunk_inter_kernel<<<BB*NC, 256>>>();
    hrec_kernel<<<BB, 128>>>(Wo + 1*LW, bo + 1*LB, out);
}

// round 17
// speedup vs baseline: 1.4298x; 1.0243x over previous
#include <cuda_runtime.h>
#include <cuda_bf16.h>
#include <cstddef>

#define BB   8
#define TT   1024
#define HH   128
#define BT   (BB*TT)
#define NC   32          // chunks per (batch,layer)
#define SS   32          // chunk size
#define LPAD 132         // smem row pitch (floats)

typedef unsigned long long ull;

// ---------------- device scratch ----------------
__device__ __align__(16) float g_Q [BT*HH];
__device__ __align__(16) float g_K [BT*HH];
__device__ __align__(16) float g_V [BT*HH];
__device__ __align__(16) float g_A [BT*HH];      // a = exp(zi) * v   (per layer)
__device__ __align__(16) float g_F [BT*HH];      // zf logits          (per layer)
__device__ __align__(16) float g_X1[BT*HH];      // layer-0 hidden output
__device__ __align__(16) float g_Attn[BT*HH];    // attn readout per layer
__device__ __align__(16) float g_Qt[BT*HH];      // q * exp(cum)
__device__ __align__(16) float g_E [BB*NC*HH];   // exp(cum_S) per (b,c,h)
__device__ __align__(16) float g_U [BB*NC*HH*HH];  // per-chunk At^T @ K
__device__ __align__(16) float g_Cb[BB*NC*HH*HH];  // C at chunk start

// ---------------- packed f32x2 helpers ----------------
__device__ __forceinline__ ull pk(float lo, float hi) {
    ull r; asm("mov.b64 %0,{%1,%2};" : "=l"(r) : "f"(lo), "f"(hi)); return r;
}
__device__ __forceinline__ void upk(ull v, float &lo, float &hi) {
    asm("mov.b64 {%0,%1},%2;" : "=f"(lo), "=f"(hi) : "l"(v));
}
__device__ __forceinline__ ull fma2(ull a, ull b, ull c) {
    ull d; asm("fma.rn.f32x2 %0,%1,%2,%3;" : "=l"(d) : "l"(a), "l"(b), "l"(c)); return d;
}
__device__ __forceinline__ ull add2(ull a, ull b) {
    ull d; asm("add.rn.f32x2 %0,%1,%2;" : "=l"(d) : "l"(a), "l"(b)); return d;
}

// ---------------- GEMM accumulation ----------------
__device__ __forceinline__ void gemm_acc(const float* xs, int rgp, int cg,
                                         const float* __restrict__ W,
                                         float acc[8][4]) {
    #pragma unroll
    for (int r = 0; r < 8; ++r) { acc[r][0]=0.f; acc[r][1]=0.f; acc[r][2]=0.f; acc[r][3]=0.f; }
    #pragma unroll 2
    for (int k4 = 0; k4 < 32; ++k4) {
        float4 xr[8];
        #pragma unroll
        for (int r = 0; r < 8; ++r)
            xr[r] = *(const float4*)&xs[(rgp*8 + r)*HH + k4*4];
        #pragma unroll
        for (int kk = 0; kk < 4; ++kk) {
            float4 w = *(const float4*)&W[(size_t)(k4*4 + kk)*HH + cg*4];
            #pragma unroll
            for (int r = 0; r < 8; ++r) {
                float xv = (kk==0) ? xr[r].x : (kk==1) ? xr[r].y : (kk==2) ? xr[r].z : xr[r].w;
                acc[r][0] = fmaf(xv, w.x, acc[r][0]);
                acc[r][1] = fmaf(xv, w.y, acc[r][1]);
                acc[r][2] = fmaf(xv, w.z, acc[r][2]);
                acc[r][3] = fmaf(xv, w.w, acc[r][3]);
            }
        }
    }
}

// MODE 0: identity -> global   MODE 2: exp * Vsrc -> global
template<int MODE>
__device__ __forceinline__ void gemm_pass(const float* xs, int row0, int rgp, int cg,
                                          const float* __restrict__ W,
                                          const float* __restrict__ bias,
                                          const float* __restrict__ Vsrc,
                                          float* __restrict__ Y) {
    float acc[8][4];
    gemm_acc(xs, rgp, cg, W, acc);
    float4 b4 = *(const float4*)&bias[cg*4];
    #pragma unroll
    for (int r = 0; r < 8; ++r) {
        size_t off = (size_t)(row0 + rgp*8 + r)*HH + cg*4;
        float4 o;
        o.x = acc[r][0] + b4.x; o.y = acc[r][1] + b4.y;
        o.z = acc[r][2] + b4.z; o.w = acc[r][3] + b4.w;
        if (MODE == 2) {
            o.x = __expf(o.x); o.y = __expf(o.y); o.z = __expf(o.z); o.w = __expf(o.w);
            float4 v = *(const float4*)&Vsrc[off];
            o.x *= v.x; o.y *= v.y; o.z *= v.z; o.w *= v.w;
        }
        *(float4*)&Y[off] = o;
    }
}

// ---------------- GEMM phase, split by pass: grid (128, 4) ----------------
__global__ __launch_bounds__(256) void mat_kernel(
    const float* __restrict__ X,
    const float* __restrict__ Wq, const float* __restrict__ bq,
    const float* __restrict__ Wk, const float* __restrict__ bk,
    const float* __restrict__ Wv, const float* __restrict__ bv,
    const float* __restrict__ Wi, const float* __restrict__ bi,
    const float* __restrict__ Wf, const float* __restrict__ bf) {
    __shared__ float xs[64*HH];
    const int tid = threadIdx.x;
    const int row0 = blockIdx.x * 64;
    for (int i = tid; i < 64*32; i += 256) {
        int r = i >> 5, c4 = i & 31;
        *(float4*)&xs[r*HH + c4*4] = *(const float4*)&X[(size_t)(row0 + r)*HH + c4*4];
    }
    __syncthreads();
    const int cg  = tid & 31;
    const int rgp = tid >> 5;
    const int y   = blockIdx.y;
    if (y == 0) {
        gemm_pass<0>(xs, row0, rgp, cg, Wq, bq, nullptr, g_Q);
    } else if (y == 1) {
        gemm_pass<0>(xs, row0, rgp, cg, Wk, bk, nullptr, g_K);
    } else if (y == 2) {
        float vacc[8][4];
        gemm_acc(xs, rgp, cg, Wv, vacc);
        float4 bv4 = *(const float4*)&bv[cg*4];
        #pragma unroll
        for (int r = 0; r < 8; ++r) {
            vacc[r][0] += bv4.x; vacc[r][1] += bv4.y;
            vacc[r][2] += bv4.z; vacc[r][3] += bv4.w;
            size_t off = (size_t)(row0 + rgp*8 + r)*HH + cg*4;
            *(float4*)&g_V[off] = make_float4(vacc[r][0], vacc[r][1], vacc[r][2], vacc[r][3]);
        }
        float iacc[8][4];
        gemm_acc(xs, rgp, cg, Wi, iacc);
        float4 bi4 = *(const float4*)&bi[cg*4];
        #pragma unroll
        for (int r = 0; r < 8; ++r) {
            size_t off = (size_t)(row0 + rgp*8 + r)*HH + cg*4;
            float4 o;
            o.x = __expf(iacc[r][0] + bi4.x) * vacc[r][0];
            o.y = __expf(iacc[r][1] + bi4.y) * vacc[r][1];
            o.z = __expf(iacc[r][2] + bi4.z) * vacc[r][2];
            o.w = __expf(iacc[r][3] + bi4.w) * vacc[r][3];
            *(float4*)&g_A[off] = o;
        }
    } else {
        gemm_pass<0>(xs, row0, rgp, cg, Wf, bf, nullptr, g_F);
    }
}

// Layer-1 gates from g_X1: grid (128, 2)
__global__ __launch_bounds__(256) void gates_kernel(
    const float* __restrict__ Wi, const float* __restrict__ bi,
    const float* __restrict__ Wf, const float* __restrict__ bf) {
    __shared__ float xs[64*HH];
    const int tid = threadIdx.x;
    const int row0 = blockIdx.x * 64;
    const float* X = (const float*)g_X1;
    for (int i = tid; i < 64*32; i += 256) {
        int r = i >> 5, c4 = i & 31;
        *(float4*)&xs[r*HH + c4*4] = *(const float4*)&X[(size_t)(row0 + r)*HH + c4*4];
    }
    __syncthreads();
    const int cg  = tid & 31;
    const int rgp = tid >> 5;
    if (blockIdx.y == 0)
        gemm_pass<2>(xs, row0, rgp, cg, Wi, bi, g_V, g_A);
    else
        gemm_pass<0>(xs, row0, rgp, cg, Wf, bf, nullptr, g_F);
}

// ---------------- chunk_local + fused cumsum: 256 CTAs ----------------
// Reordered phases (one less K load, two fewer barriers):
//  T1<-F, T2<-A -> cumsum (T1=e^cum, T2=At) -> Qt (write g_Qt AND T1 in place)
//  -> G from (T1=Qt, T2=At) -> T1<-K -> { U from (T2,T1) ; intra from (Gs,T1) }
__global__ __launch_bounds__(256, 1) void chunk_local_kernel() {
    const int b = blockIdx.x >> 5, c = blockIdx.x & 31;
    const int tid = threadIdx.x;
    const size_t tb = ((size_t)b*TT + (size_t)c*SS) * HH;

    __shared__ float T1[SS][LPAD];
    __shared__ float T2[SS][LPAD];
    __shared__ float Gs[SS][SS+1];

    #pragma unroll
    for (int k = 0; k < 4; ++k) {
        int i = tid + k*256, s = i >> 5, c4 = i & 31;
        *(float4*)&T1[s][c4*4] = *(const float4*)&g_F[tb + (size_t)s*HH + c4*4];
        *(float4*)&T2[s][c4*4] = *(const float4*)&g_A[tb + (size_t)s*HH + c4*4];
    }
    __syncthreads();

    // cumsum along s for column h (tid<128)
    if (tid < 128) {
        const int h = tid;
        float cum = 0.f, e = 1.f;
        #pragma unroll 4
        for (int s = 0; s < SS; ++s) {
            cum += T1[s][h];
            e = __expf(cum);
            T1[s][h] = e;                       // e^{+cum}
            T2[s][h] *= __expf(-cum);           // At
        }
        g_E[(size_t)(b*NC + c)*HH + h] = e;
    }
    __syncthreads();

    // Qt = Q * e^{+cum} -> g_Qt and T1 in place (same-thread same-element overwrite)
    #pragma unroll
    for (int k = 0; k < 4; ++k) {
        int i = tid + k*256, s = i >> 5, c4 = i & 31;
        float4 q = *(const float4*)&g_Q[tb + (size_t)s*HH + c4*4];
        float4 e4 = *(const float4*)&T1[s][c4*4];
        q.x *= e4.x; q.y *= e4.y; q.z *= e4.z; q.w *= e4.w;
        *(float4*)&g_Qt[tb + (size_t)s*HH + c4*4] = q;
        *(float4*)&T1[s][c4*4] = q;             // Qt now in T1
    }
    __syncthreads();

    // G[t][s] = sum_h Qt[t][h]*At[s][h], causal mask s<=t
    #pragma unroll
    for (int i2 = 0; i2 < 4; ++i2) {
        int e = tid*4 + i2, t = e >> 5, s = e & 31;
        float d0=0.f, d1=0.f, d2=0.f, d3=0.f;
        for (int h = 0; h < HH; h += 4) {
            d0 = fmaf(T1[t][h+0], T2[s][h+0], d0);
            d1 = fmaf(T1[t][h+1], T2[s][h+1], d1);
            d2 = fmaf(T1[t][h+2], T2[s][h+2], d2);
            d3 = fmaf(T1[t][h+3], T2[s][h+3], d3);
        }
        Gs[t][s] = (s <= t) ? ((d0+d1)+(d2+d3)) : 0.f;
    }
    __syncthreads();

    // T1 <- K (single K load for both U and intra)
    #pragma unroll
    for (int k = 0; k < 4; ++k) {
        int i = tid + k*256, s = i >> 5, c4 = i & 31;
        *(float4*)&T1[s][c4*4] = *(const float4*)&g_K[tb + (size_t)s*HH + c4*4];
    }
    __syncthreads();

    // U[h][j] = sum_s At[s][h] * K[s][j]
    {
        const int ty = tid >> 4, tx = tid & 15;
        const int h0 = ty*8, j0 = tx*8;
        float acc[8][8];
        #pragma unroll
        for (int r = 0; r < 8; ++r)
            #pragma unroll
            for (int q = 0; q < 8; ++q) acc[r][q] = 0.f;
        for (int s = 0; s < SS; ++s) {
            float av[8], kv[8];
            #pragma unroll
            for (int r = 0; r < 8; ++r) av[r] = T2[s][h0+r];
            #pragma unroll
            for (int q = 0; q < 8; ++q) kv[q] = T1[s][j0+q];
            #pragma unroll
            for (int r = 0; r < 8; ++r)
                #pragma unroll
                for (int q = 0; q < 8; ++q) acc[r][q] = fmaf(av[r], kv[q], acc[r][q]);
        }
        const size_t ub = (size_t)(b*NC + c) * (HH*HH);
        #pragma unroll
        for (int r = 0; r < 8; ++r) {
            *(float4*)&g_U[ub + (size_t)(h0+r)*HH + j0]     = make_float4(acc[r][0], acc[r][1], acc[r][2], acc[r][3]);
            *(float4*)&g_U[ub + (size_t)(h0+r)*HH + j0 + 4] = make_float4(acc[r][4], acc[r][5], acc[r][6], acc[r][7]);
        }
    }

    // intra[t][j] = sum_s Gs[t][s]*K[s][j]  (same phase: all smem read-only now)
    {
        const int t = tid >> 3, j0 = (tid & 7) * 16;
        float acc[16];
        #pragma unroll
        for (int q = 0; q < 16; ++q) acc[q] = 0.f;
        for (int s = 0; s < SS; ++s) {
            float g = Gs[t][s];
            #pragma unroll
            for (int q = 0; q < 16; ++q) acc[q] = fmaf(g, T1[s][j0+q], acc[q]);
        }
        #pragma unroll
        for (int jj = 0; jj < 4; ++jj)
            *(float4*)&g_Attn[tb + (size_t)t*HH + j0 + jj*4] =
                make_float4(acc[jj*4], acc[jj*4+1], acc[jj*4+2], acc[jj*4+3]);
    }
}

// ---------------- chunk combine, 128 CTAs ----------------
__global__ __launch_bounds__(256, 1) void combine_kernel() {
    const int b  = blockIdx.x >> 4;
    const int hs = blockIdx.x & 15;
    const int tid = threadIdx.x;
    const int r  = hs*8 + (tid >> 5);
    const int c4 = tid & 31;

    const float4* U4 = (const float4*)g_U;
    float4* Cb4 = (float4*)g_Cb;
    const int elem = r*32 + c4;

    float4 C = make_float4(0.f, 0.f, 0.f, 0.f);
    size_t m0 = ((size_t)(b*NC) << 12) + elem;
    float4 u = __ldg(&U4[m0]);
    float  e = __ldg(&g_E[(size_t)(b*NC)*HH + r]);

    for (int c = 0; c < NC; ++c) {
        float4 un; float en;
        if (c + 1 < NC) {
            size_t mn = ((size_t)(b*NC + c + 1) << 12) + elem;
            un = __ldg(&U4[mn]);
            en = __ldg(&g_E[(size_t)(b*NC + c + 1)*HH + r]);
        } else { un = u; en = e; }
        Cb4[((size_t)(b*NC + c) << 12) + elem] = C;
        C.x = e*(C.x + u.x); C.y = e*(C.y + u.y);
        C.z = e*(C.z + u.z); C.w = e*(C.w + u.w);
        u = un; e = en;
    }
}

// ---------------- chunk_inter, register-tiled 4x4: attn += Qt @ Cb ----------------
__global__ __launch_bounds__(256, 1) void chunk_inter_kernel() {
    const int b = blockIdx.x >> 5, c = blockIdx.x & 31;
    const int tid = threadIdx.x;
    const size_t tb = ((size_t)b*TT + (size_t)c*SS) * HH;
    const size_t cb = (size_t)(b*NC + c) * (HH*HH);

    __shared__ float tQ[SS][LPAD];
    __shared__ float tC[32][LPAD];

    #pragma unroll
    for (int k = 0; k < 4; ++k) {
        int i = tid + k*256, s = i >> 5, c4 = i & 31;
        *(float4*)&tQ[s][c4*4] = *(const float4*)&g_Qt[tb + (size_t)s*HH + c4*4];
    }

    const int t0 = (tid >> 5) * 4;
    const int j0 = (tid & 31) * 4;
    float acc[4][4];
    #pragma unroll
    for (int r = 0; r < 4; ++r)
        #pragma unroll
        for (int q = 0; q < 4; ++q) acc[r][q] = 0.f;

    for (int hb = 0; hb < 4; ++hb) {
        __syncthreads();
        #pragma unroll
        for (int k = 0; k < 4; ++k) {
            int i = tid + k*256, s = i >> 5, c4 = i & 31;
            *(float4*)&tC[s][c4*4] = *(const float4*)&g_Cb[cb + (size_t)(hb*32 + s)*HH + c4*4];
        }
        __syncthreads();
        #pragma unroll 4
        for (int hh = 0; hh < 32; ++hh) {
            float4 cv = *(const float4*)&tC[hh][j0];
            float q0 = tQ[t0+0][hb*32 + hh];
            float q1 = tQ[t0+1][hb*32 + hh];
            float q2 = tQ[t0+2][hb*32 + hh];
            float q3 = tQ[t0+3][hb*32 + hh];
            acc[0][0] = fmaf(q0, cv.x, acc[0][0]); acc[0][1] = fmaf(q0, cv.y, acc[0][1]);
            acc[0][2] = fmaf(q0, cv.z, acc[0][2]); acc[0][3] = fmaf(q0, cv.w, acc[0][3]);
            acc[1][0] = fmaf(q1, cv.x, acc[1][0]); acc[1][1] = fmaf(q1, cv.y, acc[1][1]);
            acc[1][2] = fmaf(q1, cv.z, acc[1][2]); acc[1][3] = fmaf(q1, cv.w, acc[1][3]);
            acc[2][0] = fmaf(q2, cv.x, acc[2][0]); acc[2][1] = fmaf(q2, cv.y, acc[2][1]);
            acc[2][2] = fmaf(q2, cv.z, acc[2][2]); acc[2][3] = fmaf(q2, cv.w, acc[2][3]);
            acc[3][0] = fmaf(q3, cv.x, acc[3][0]); acc[3][1] = fmaf(q3, cv.y, acc[3][1]);
            acc[3][2] = fmaf(q3, cv.z, acc[3][2]); acc[3][3] = fmaf(q3, cv.w, acc[3][3]);
        }
    }

    #pragma unroll
    for (int r = 0; r < 4; ++r) {
        size_t off = tb + (size_t)(t0 + r)*HH + j0;
        float4 v = *(const float4*)&g_Attn[off];
        v.x += acc[r][0]; v.y += acc[r][1]; v.z += acc[r][2]; v.w += acc[r][3];
        *(float4*)&g_Attn[off] = v;
    }
}

// ---------------- h recurrence: column-per-thread, 4-chain fold ----------------
__global__ __launch_bounds__(128, 1) void hrec_kernel(
    const float* __restrict__ Wo, const float* __restrict__ bo,
    float* __restrict__ Xout_param) {
    const int b = blockIdx.x;
    const int j = threadIdx.x;
    const float NL2E = -1.44269504088896f;

    __shared__ __align__(16) float hbuf[2][HH];

    float* Xout = Xout_param ? Xout_param : g_X1;
    const size_t base = (size_t)b * TT * HH;
    const float* Attnb = g_Attn + base;

    ull w2[64];
    #pragma unroll
    for (int p = 0; p < 64; ++p)
        w2[p] = pk(NL2E * Wo[(size_t)(2*p)*HH + j],
                   NL2E * Wo[(size_t)(2*p + 1)*HH + j]);
    const ull bseed = pk(NL2E * bo[j], 0.f);

    hbuf[0][j] = 0.f;

    float ring[8];
    #pragma unroll
    for (int u = 0; u < 8; ++u)
        ring[u] = __ldg(Attnb + (size_t)u*HH + j);

    for (int tb = 0; tb < TT; tb += 8) {
        #pragma unroll
        for (int u = 0; u < 8; ++u) {
            const int t = tb + u;
            __syncthreads();

            const ulonglong2* hb2 = (const ulonglong2*)hbuf[t & 1];
            ull s0 = bseed, s1 = 0ull, s2 = 0ull, s3 = 0ull;
            #pragma unroll
            for (int k = 0; k < 32; ++k) {
                ulonglong2 hh = hb2[k];
                if (k & 1) { s2 = fma2(hh.x, w2[2*k], s2); s3 = fma2(hh.y, w2[2*k+1], s3); }
                else       { s0 = fma2(hh.x, w2[2*k], s0); s1 = fma2(hh.y, w2[2*k+1], s1); }
            }
            float rnext = 0.f;
            if (t + 8 < TT) rnext = __ldg(Attnb + (size_t)(t + 8)*HH + j);

            ull st = add2(add2(s0, s1), add2(s2, s3));
            float lo, hi; upk(st, lo, hi);
            float zl = lo + hi;
            float ex; asm("ex2.approx.f32 %0, %1;" : "=f"(ex) : "f"(zl));
            float den = 1.0f + ex;
            float o;  asm("rcp.approx.f32 %0, %1;" : "=f"(o) : "f"(den));
            float h = o * ring[u];
            hbuf[(t & 1) ^ 1][j] = h;
            Xout[base + (size_t)t*HH + j] = h;
            ring[u] = rnext;
        }
    }
}

// ---------------- launch ----------------
extern "C" void kernel_launch(void* const* d_in, const int* in_sizes, int n_in,
                              void* d_out, int out_size) {
    const float* X  = (const float*)d_in[0];
    const float* Wq = (const float*)d_in[1];
    const float* bq = (const float*)d_in[2];
    const float* Wk = (const float*)d_in[3];
    const float* bk = (const float*)d_in[4];
    const float* Wv = (const float*)d_in[5];
    const float* bv = (const float*)d_in[6];
    const float* Wi = (const float*)d_in[7];
    const float* bi = (const float*)d_in[8];
    const float* Wf = (const float*)d_in[9];
    const float* bf = (const float*)d_in[10];
    const float* Wo = (const float*)d_in[11];
    const float* bo = (const float*)d_in[12];
    float* out = (float*)d_out;

    const int LW = HH*HH;
    const int LB = HH;

    mat_kernel<<<dim3(BT/64, 4), 256>>>(X, Wq, bq, Wk, bk, Wv, bv,
                                        Wi + 0*LW, bi + 0*LB, Wf + 0*LW, bf + 0*LB);
    chunk_local_kernel<<<BB*NC, 256>>>();
    combine_kernel<<<BB*16, 256>>>();
    chunk_inter_kernel<<<BB*NC, 256>>>();
    hrec_kernel<<<BB, 128>>>(Wo + 0*LW, bo + 0*LB, nullptr);   // -> g_X1

    gates_kernel<<<dim3(BT/64, 2), 256>>>(Wi + 1*LW, bi + 1*LB, Wf + 1*LW, bf + 1*LB);
    chunk_local_kernel<<<BB*NC, 256>>>();
    combine_kernel<<<BB*16, 256>>>();
    chunk_inter_kernel<<<BB*NC, 256>>>();
    hrec_kernel<<<BB, 128>>>(Wo + 1*LW, bo + 1*LB, out);
}